// round 10
// baseline (speedup 1.0000x reference)
#include <cuda_runtime.h>
#include <math.h>

#define NB 32
#define NC 1024
#define NM 1024
#define ND 512
#define NR 64

#define CS_SPLIT 32             // c-chunks for p2a (32 c each)
#define KS_SPLIT 16             // d-chunks for p2b (32 d each)
#define SCH 32                  // c-chunks for k_s (32 c each)
#define D_CH (ND / KS_SPLIT)    // 32
#define C_CH (NC / SCH)         // 32
#define ITILE 128               // i-tile for k_wout
#define STAGES 8                // cp.async ring depth in k_s
#define TS_ROWS 12              // rows per block in k_tsum (48KB smem)

// ---- device scratch (static: no allocations allowed) ----
__device__ float g_tsum[NB * NC];
__device__ float g_rsum[NR];
__device__ float g_kpart[CS_SPLIT][NB * ND];
__device__ float g_vpart[CS_SPLIT][NB * ND];
__device__ float g_upart[KS_SPLIT][NB * NC];
__device__ float g_ypart[KS_SPLIT][NB * NC];
__device__ float g_spart[SCH][NB * NM];

__device__ __forceinline__ float warp_sum(float v) {
    #pragma unroll
    for (int o = 16; o; o >>= 1) v += __shfl_down_sync(0xffffffffu, v, o);
    return v;
}

// cp.async: 16B global->shared, no register destination (ptxas cannot collapse)
__device__ __forceinline__ void cpasync16(float* sdst, const float* gsrc) {
    unsigned s = (unsigned)__cvta_generic_to_shared(sdst);
    asm volatile("cp.async.cg.shared.global [%0], [%1], 16;" :: "r"(s), "l"(gsrc));
}
__device__ __forceinline__ void cp_commit()   { asm volatile("cp.async.commit_group;"); }
__device__ __forceinline__ void cp_wait_all() { asm volatile("cp.async.wait_group 0;"); }

// ---------------------------------------------------------------------------
// k_tsum: 192 threads, 12 rows/block (2 per warp). Each thread keeps 16
// cp.async copies in flight, then reduces its own bytes from smem.
// Rows [0, NB*NC) are T; rows [NB*NC, NB*NC+NR) are R_full.
// ---------------------------------------------------------------------------
__global__ __launch_bounds__(192) void k_tsum(const float* __restrict__ T,
                                              const float* __restrict__ Rf) {
    __shared__ __align__(16) float buf[TS_ROWS][NM];   // 48KB
    int wid  = threadIdx.x >> 5;        // 0..5
    int lane = threadIdx.x & 31;
    int base = blockIdx.x * TS_ROWS + wid * 2;

    #pragma unroll
    for (int rr = 0; rr < 2; rr++) {
        int row = base + rr;
        const float* src = (row < NB * NC)
            ? T  + (size_t)row * NM
            : Rf + (size_t)(row - NB * NC) * NM;
        #pragma unroll
        for (int k = 0; k < 8; k++)
            cpasync16(&buf[wid * 2 + rr][k * 128 + lane * 4],
                      src + (k * 32 + lane) * 4);
    }
    cp_commit();
    cp_wait_all();

    #pragma unroll
    for (int rr = 0; rr < 2; rr++) {
        int row = base + rr;
        float acc = 0.f;
        #pragma unroll
        for (int k = 0; k < 8; k++) {
            float4 v = *reinterpret_cast<float4*>(&buf[wid * 2 + rr][k * 128 + lane * 4]);
            acc += (v.x + v.y) + (v.z + v.w);
        }
        acc = warp_sum(acc);
        if (lane == 0) {
            if (row < NB * NC) g_tsum[row] = acc;
            else               g_rsum[row - NB * NC] = acc;
        }
    }
}

// ---------------------------------------------------------------------------
// k_p2a: kpart/vpart[cs][b,d] = sum_{c in chunk} tsum[b,c]*Wk/Wv[c,d]
// grid (ND/128, CS_SPLIT) x 128; thread owns d, acc[32] over b.
// ---------------------------------------------------------------------------
__global__ __launch_bounds__(128) void k_p2a(const float* __restrict__ Wk,
                                             const float* __restrict__ Wv) {
    __shared__ float ts[NB][32];
    int d  = blockIdx.x * 128 + threadIdx.x;
    int c0 = blockIdx.y * 32;
    for (int e = threadIdx.x; e < NB * 32; e += 128)
        ts[e >> 5][e & 31] = g_tsum[(e >> 5) * NC + c0 + (e & 31)];
    __syncthreads();

    float aK[NB], aV[NB];
    #pragma unroll
    for (int b = 0; b < NB; b++) { aK[b] = 0.f; aV[b] = 0.f; }

    #pragma unroll 4
    for (int cc = 0; cc < 32; cc++) {
        int c = c0 + cc;
        float wk = Wk[(size_t)c * ND + d];
        float wv = Wv[(size_t)c * ND + d];
        #pragma unroll
        for (int b = 0; b < NB; b++) {
            float tv = ts[b][cc];
            aK[b] = fmaf(tv, wk, aK[b]);
            aV[b] = fmaf(tv, wv, aV[b]);
        }
    }
    #pragma unroll
    for (int b = 0; b < NB; b++) {
        g_kpart[blockIdx.y][b * ND + d] = aK[b];
        g_vpart[blockIdx.y][b * ND + d] = aV[b];
    }
}

// ---------------------------------------------------------------------------
// k_p2b: fuses kv-partial reduction + both GEMMs (no Wq transpose).
// ---------------------------------------------------------------------------
__global__ __launch_bounds__(128) void k_p2b(const float* __restrict__ Wq,
                                             const float* __restrict__ Wout) {
    __shared__ float ks[NB][D_CH], vs[NB][D_CH];
    int c  = blockIdx.x * 128 + threadIdx.x;
    int d0 = blockIdx.y * D_CH;

    for (int e = threadIdx.x; e < NB * D_CH; e += 128) {
        int addr = (e >> 5) * ND + d0 + (e & (D_CH - 1));
        float sk = 0.f, sv = 0.f;
        #pragma unroll
        for (int p = 0; p < CS_SPLIT; p++) {
            sk += g_kpart[p][addr];
            sv += g_vpart[p][addr];
        }
        ks[e >> 5][e & (D_CH - 1)] = sk;
        vs[e >> 5][e & (D_CH - 1)] = sv;
    }
    __syncthreads();

    float wqr[D_CH];
    {
        const float4* wq4 = reinterpret_cast<const float4*>(Wq + (size_t)c * ND + d0);
        #pragma unroll
        for (int q = 0; q < D_CH / 4; q++) {
            float4 v = wq4[q];
            wqr[q * 4 + 0] = v.x; wqr[q * 4 + 1] = v.y;
            wqr[q * 4 + 2] = v.z; wqr[q * 4 + 3] = v.w;
        }
    }

    float aU[NB], aY[NB];
    #pragma unroll
    for (int b = 0; b < NB; b++) { aU[b] = 0.f; aY[b] = 0.f; }

    #pragma unroll 4
    for (int dd = 0; dd < D_CH; dd++) {
        float wq = wqr[dd];
        float wo = Wout[(size_t)(d0 + dd) * NC + c];
        #pragma unroll
        for (int b = 0; b < NB; b++) {
            aU[b] = fmaf(ks[b][dd], wq, aU[b]);
            aY[b] = fmaf(vs[b][dd], wo, aY[b]);
        }
    }
    #pragma unroll
    for (int b = 0; b < NB; b++) {
        g_upart[blockIdx.y][b * NC + c] = aU[b];
        g_ypart[blockIdx.y][b * NC + c] = aY[b];
    }
}

// ---------------------------------------------------------------------------
// k_s: fuses u-reduction. spart[ch][b,i] = sum_{c in chunk} u[b,c]*T[b,c,i]
// grid (SCH, NB) = 1024 blocks x 256. Thread-local 8-stage cp.async ring:
// each thread copies and later consumes exactly its own 16B per row, so no
// block sync is needed and 8 copies stay in flight regardless of regalloc.
// ---------------------------------------------------------------------------
__global__ __launch_bounds__(256) void k_s(const float* __restrict__ T) {
    __shared__ float us[C_CH];
    __shared__ __align__(16) float buf[STAGES][NM];    // 32KB ring
    int b  = blockIdx.y;
    int c0 = blockIdx.x * C_CH;
    if (threadIdx.x < C_CH) {
        float u = 0.f;
        #pragma unroll
        for (int p = 0; p < KS_SPLIT; p++)
            u += g_upart[p][b * NC + c0 + threadIdx.x];
        us[threadIdx.x] = u;
    }
    __syncthreads();

    const float* Tb = T + ((size_t)b * NC + c0) * NM + 4 * threadIdx.x;
    float* slot = &buf[0][4 * threadIdx.x];

    #pragma unroll
    for (int cc = 0; cc < STAGES; cc++) {
        cpasync16(slot + cc * NM, Tb + (size_t)cc * NM);
        cp_commit();
    }

    float4 acc = {0.f, 0.f, 0.f, 0.f};
    #pragma unroll
    for (int cc = 0; cc < C_CH; cc++) {
        asm volatile("cp.async.wait_group %0;" :: "n"(STAGES - 1));
        float4 t = *reinterpret_cast<float4*>(slot + (cc & (STAGES - 1)) * NM);
        if (cc + STAGES < C_CH)
            cpasync16(slot + (cc & (STAGES - 1)) * NM, Tb + (size_t)(cc + STAGES) * NM);
        cp_commit();
        float u = us[cc];
        acc.x = fmaf(u, t.x, acc.x);
        acc.y = fmaf(u, t.y, acc.y);
        acc.z = fmaf(u, t.z, acc.z);
        acc.w = fmaf(u, t.w, acc.w);
    }
    reinterpret_cast<float4*>(g_spart[blockIdx.x] + b * NM)[threadIdx.x] = acc;
}

// ---------------------------------------------------------------------------
// k_wout: fuses s-reduction + softmax + y-reduction + output write.
// grid (NM/ITILE, NB) = 256 blocks x 256 threads.
// ---------------------------------------------------------------------------
__global__ __launch_bounds__(256) void k_wout(float* __restrict__ out) {
    __shared__ __align__(16) float w_s[ITILE];
    __shared__ float y_s[NC];
    __shared__ float rs[NR];
    int b  = blockIdx.y;
    int i0 = blockIdx.x * ITILE;
    int tid = threadIdx.x;

    // phase A: rsum to smem + y reduction
    if (tid < NR) rs[tid] = g_rsum[tid];
    for (int e = tid; e < NC; e += 256) {
        float y = 0.f;
        #pragma unroll
        for (int p = 0; p < KS_SPLIT; p++)
            y += g_ypart[p][b * NC + e];
        y_s[e] = y;
    }
    __syncthreads();

    // phase B: s reduction + 64-wide softmax -> w (threads < ITILE)
    if (tid < ITILE) {
        int i = i0 + tid;
        float s = 0.f;
        #pragma unroll
        for (int p = 0; p < SCH; p++) s += g_spart[p][b * NM + i];
        s *= 0.044194173824159216f;   // 1/sqrt(512)

        float mx = -1e30f;
        #pragma unroll
        for (int r = 0; r < NR; r++) mx = fmaxf(mx, s * rs[r]);
        float sp = 0.f, spr = 0.f;
        #pragma unroll
        for (int r = 0; r < NR; r++) {
            float p = __expf(fmaf(s, rs[r], -mx));
            sp += p;
            spr = fmaf(p, rs[r], spr);
        }
        w_s[tid] = spr / sp;
    }
    __syncthreads();

    // phase C: out[b,c,i0:i0+128] = w * y[c]; 8 c's x 32 float4-lanes per pass
    int ci = tid >> 5;                 // 0..7
    int i4 = tid & 31;                 // float4 lane within i-tile
    float4 w4 = reinterpret_cast<const float4*>(w_s)[i4];
    float4* O4 = reinterpret_cast<float4*>(out);
    #pragma unroll 4
    for (int c = ci; c < NC; c += 8) {
        float yv = y_s[c];
        float4 o;
        o.x = w4.x * yv; o.y = w4.y * yv; o.z = w4.z * yv; o.w = w4.w * yv;
        O4[((size_t)(b * NC + c) * NM + i0) / 4 + i4] = o;
    }
}

// ---------------------------------------------------------------------------
extern "C" void kernel_launch(void* const* d_in, const int* in_sizes, int n_in,
                              void* d_out, int out_size) {
    const float* T    = (const float*)d_in[0];
    const float* Wq   = (const float*)d_in[1];
    const float* Wk   = (const float*)d_in[2];
    const float* Wv   = (const float*)d_in[3];
    const float* Wout = (const float*)d_in[4];
    const float* Rf   = (const float*)d_in[5];
    float* out = (float*)d_out;

    k_tsum<<<(NB * NC + NR) / TS_ROWS, 192>>>(T, Rf);   // 2736 blocks
    k_p2a<<<dim3(ND / 128, CS_SPLIT), 128>>>(Wk, Wv);
    k_p2b<<<dim3(NC / 128, KS_SPLIT), 128>>>(Wq, Wout);
    k_s<<<dim3(SCH, NB), 256>>>(T);
    k_wout<<<dim3(NM / ITILE, NB), 256>>>(out);
}

// round 12
// speedup vs baseline: 1.0039x; 1.0039x over previous
#include <cuda_runtime.h>
#include <math.h>

#define NB 32
#define NC 1024
#define NM 1024
#define ND 512
#define NR 64

#define CS_SPLIT 32             // c-chunks for p2a (32 c each)
#define KS_SPLIT 16             // d-chunks for p2b (32 d each)
#define SCH 32                  // c-chunks for k_s (32 c each)
#define D_CH (ND / KS_SPLIT)    // 32
#define C_CH (NC / SCH)         // 32
#define ITILE 128               // i-tile for k_wout
#define WSPLIT 2                // c-halves for k_wout

// ---- device scratch (static: no allocations allowed) ----
__device__ float g_tsum[NB * NC];
__device__ float g_rsum[NR];
__device__ float g_kpart[CS_SPLIT][NB * ND];
__device__ float g_vpart[CS_SPLIT][NB * ND];
__device__ float g_upart[KS_SPLIT][NB * NC];
__device__ float g_ypart[KS_SPLIT][NB * NC];
__device__ float g_spart[SCH][NB * NM];

__device__ __forceinline__ float warp_sum(float v) {
    #pragma unroll
    for (int o = 16; o; o >>= 1) v += __shfl_down_sync(0xffffffffu, v, o);
    return v;
}

// ---------------------------------------------------------------------------
// k_tsum: blocks [0,4096): tsum[b,c] = sum_m T[b,c,m]  (warp/row, float4)
//         blocks [4096,4104): rsum[r] = sum_m R_full[r,m]
// (R7 form — best measured)
// ---------------------------------------------------------------------------
__global__ __launch_bounds__(256) void k_tsum(const float* __restrict__ T,
                                              const float* __restrict__ Rf) {
    if (blockIdx.x < 4096) {
        int row = blockIdx.x * 8 + (threadIdx.x >> 5);
        int lane = threadIdx.x & 31;
        const float4* T4 = reinterpret_cast<const float4*>(T) + (size_t)row * (NM / 4);
        float4 t[8];
        #pragma unroll
        for (int k = 0; k < 8; k++) t[k] = T4[k * 32 + lane];
        float acc = 0.f;
        #pragma unroll
        for (int k = 0; k < 8; k++)
            acc += (t[k].x + t[k].y) + (t[k].z + t[k].w);
        acc = warp_sum(acc);
        if (lane == 0) g_tsum[row] = acc;
    } else {
        int r = (blockIdx.x - 4096) * 8 + (threadIdx.x >> 5);   // 64 rows
        int lane = threadIdx.x & 31;
        const float4* R4 = reinterpret_cast<const float4*>(Rf) + (size_t)r * (NM / 4);
        float4 t[8];
        #pragma unroll
        for (int k = 0; k < 8; k++) t[k] = R4[k * 32 + lane];
        float acc = 0.f;
        #pragma unroll
        for (int k = 0; k < 8; k++)
            acc += (t[k].x + t[k].y) + (t[k].z + t[k].w);
        acc = warp_sum(acc);
        if (lane == 0) g_rsum[r] = acc;
    }
}

// ---------------------------------------------------------------------------
// k_p2a: kpart/vpart[cs][b,d] = sum_{c in chunk} tsum[b,c]*Wk/Wv[c,d]
// ---------------------------------------------------------------------------
__global__ __launch_bounds__(128) void k_p2a(const float* __restrict__ Wk,
                                             const float* __restrict__ Wv) {
    __shared__ float ts[NB][32];
    int d  = blockIdx.x * 128 + threadIdx.x;
    int c0 = blockIdx.y * 32;
    for (int e = threadIdx.x; e < NB * 32; e += 128)
        ts[e >> 5][e & 31] = g_tsum[(e >> 5) * NC + c0 + (e & 31)];
    __syncthreads();

    float aK[NB], aV[NB];
    #pragma unroll
    for (int b = 0; b < NB; b++) { aK[b] = 0.f; aV[b] = 0.f; }

    #pragma unroll 4
    for (int cc = 0; cc < 32; cc++) {
        int c = c0 + cc;
        float wk = Wk[(size_t)c * ND + d];
        float wv = Wv[(size_t)c * ND + d];
        #pragma unroll
        for (int b = 0; b < NB; b++) {
            float tv = ts[b][cc];
            aK[b] = fmaf(tv, wk, aK[b]);
            aV[b] = fmaf(tv, wv, aV[b]);
        }
    }
    #pragma unroll
    for (int b = 0; b < NB; b++) {
        g_kpart[blockIdx.y][b * ND + d] = aK[b];
        g_vpart[blockIdx.y][b * ND + d] = aV[b];
    }
}

// ---------------------------------------------------------------------------
// k_p2b: fuses kv-partial reduction + both GEMMs (no Wq transpose).
// ---------------------------------------------------------------------------
__global__ __launch_bounds__(128) void k_p2b(const float* __restrict__ Wq,
                                             const float* __restrict__ Wout) {
    __shared__ float ks[NB][D_CH], vs[NB][D_CH];
    int c  = blockIdx.x * 128 + threadIdx.x;
    int d0 = blockIdx.y * D_CH;

    for (int e = threadIdx.x; e < NB * D_CH; e += 128) {
        int addr = (e >> 5) * ND + d0 + (e & (D_CH - 1));
        float sk = 0.f, sv = 0.f;
        #pragma unroll
        for (int p = 0; p < CS_SPLIT; p++) {
            sk += g_kpart[p][addr];
            sv += g_vpart[p][addr];
        }
        ks[e >> 5][e & (D_CH - 1)] = sk;
        vs[e >> 5][e & (D_CH - 1)] = sv;
    }
    __syncthreads();

    float wqr[D_CH];
    {
        const float4* wq4 = reinterpret_cast<const float4*>(Wq + (size_t)c * ND + d0);
        #pragma unroll
        for (int q = 0; q < D_CH / 4; q++) {
            float4 v = wq4[q];
            wqr[q * 4 + 0] = v.x; wqr[q * 4 + 1] = v.y;
            wqr[q * 4 + 2] = v.z; wqr[q * 4 + 3] = v.w;
        }
    }

    float aU[NB], aY[NB];
    #pragma unroll
    for (int b = 0; b < NB; b++) { aU[b] = 0.f; aY[b] = 0.f; }

    #pragma unroll 4
    for (int dd = 0; dd < D_CH; dd++) {
        float wq = wqr[dd];
        float wo = Wout[(size_t)(d0 + dd) * NC + c];
        #pragma unroll
        for (int b = 0; b < NB; b++) {
            aU[b] = fmaf(ks[b][dd], wq, aU[b]);
            aY[b] = fmaf(vs[b][dd], wo, aY[b]);
        }
    }
    #pragma unroll
    for (int b = 0; b < NB; b++) {
        g_upart[blockIdx.y][b * NC + c] = aU[b];
        g_ypart[blockIdx.y][b * NC + c] = aY[b];
    }
}

// ---------------------------------------------------------------------------
// k_s: fuses u-reduction. spart[ch][b,i] = sum_{c in chunk} u[b,c]*T[b,c,i]
// (R7 form — best measured: plain float4 with 8-deep source batch)
// ---------------------------------------------------------------------------
__global__ __launch_bounds__(256) void k_s(const float* __restrict__ T) {
    __shared__ float us[C_CH];
    int b  = blockIdx.y;
    int c0 = blockIdx.x * C_CH;
    if (threadIdx.x < C_CH) {
        float u = 0.f;
        #pragma unroll
        for (int p = 0; p < KS_SPLIT; p++)
            u += g_upart[p][b * NC + c0 + threadIdx.x];
        us[threadIdx.x] = u;
    }
    __syncthreads();

    const float4* T4 = reinterpret_cast<const float4*>(T)
                     + ((size_t)b * NC + c0) * (NM / 4) + threadIdx.x;
    float4 acc = {0.f, 0.f, 0.f, 0.f};
    #pragma unroll
    for (int cc = 0; cc < C_CH; cc += 8) {
        float4 t[8];
        #pragma unroll
        for (int j = 0; j < 8; j++)
            t[j] = T4[(size_t)(cc + j) * (NM / 4)];
        #pragma unroll
        for (int j = 0; j < 8; j++) {
            float u = us[cc + j];
            acc.x = fmaf(u, t[j].x, acc.x);
            acc.y = fmaf(u, t[j].y, acc.y);
            acc.z = fmaf(u, t[j].z, acc.z);
            acc.w = fmaf(u, t[j].w, acc.w);
        }
    }
    reinterpret_cast<float4*>(g_spart[blockIdx.x] + b * NM)[threadIdx.x] = acc;
}

// ---------------------------------------------------------------------------
// k_wout: fuses s-reduction + softmax + y-reduction + output write.
// grid (NM/ITILE, NB, WSPLIT) = 512 blocks x 256 threads; z picks a c-half,
// doubling store-stream warps per SM. Softmax recomputed per half (cheap).
// ---------------------------------------------------------------------------
__global__ __launch_bounds__(256) void k_wout(float* __restrict__ out) {
    __shared__ __align__(16) float w_s[ITILE];
    __shared__ float y_s[NC / WSPLIT];
    __shared__ float rs[NR];
    int b   = blockIdx.y;
    int i0  = blockIdx.x * ITILE;
    int ch0 = blockIdx.z * (NC / WSPLIT);
    int tid = threadIdx.x;

    // phase A: rsum to smem + y reduction for this c-half
    if (tid < NR) rs[tid] = g_rsum[tid];
    for (int e = tid; e < NC / WSPLIT; e += 256) {
        float y = 0.f;
        #pragma unroll
        for (int p = 0; p < KS_SPLIT; p++)
            y += g_ypart[p][b * NC + ch0 + e];
        y_s[e] = y;
    }
    __syncthreads();

    // phase B: s reduction + 64-wide softmax -> w (threads < ITILE)
    if (tid < ITILE) {
        int i = i0 + tid;
        float s = 0.f;
        #pragma unroll
        for (int p = 0; p < SCH; p++) s += g_spart[p][b * NM + i];
        s *= 0.044194173824159216f;   // 1/sqrt(512)

        float mx = -1e30f;
        #pragma unroll
        for (int r = 0; r < NR; r++) mx = fmaxf(mx, s * rs[r]);
        float sp = 0.f, spr = 0.f;
        #pragma unroll
        for (int r = 0; r < NR; r++) {
            float p = __expf(fmaf(s, rs[r], -mx));
            sp += p;
            spr = fmaf(p, rs[r], spr);
        }
        w_s[tid] = spr / sp;
    }
    __syncthreads();

    // phase C: out[b, c-half, i0:i0+128] = w * y[c]
    int ci = tid >> 5;                 // 0..7
    int i4 = tid & 31;                 // float4 lane within i-tile
    float4 w4 = reinterpret_cast<const float4*>(w_s)[i4];
    float4* O4 = reinterpret_cast<float4*>(out);
    #pragma unroll 4
    for (int c = ci; c < NC / WSPLIT; c += 8) {
        float yv = y_s[c];
        float4 o;
        o.x = w4.x * yv; o.y = w4.y * yv; o.z = w4.z * yv; o.w = w4.w * yv;
        O4[((size_t)(b * NC + ch0 + c) * NM + i0) / 4 + i4] = o;
    }
}

// ---------------------------------------------------------------------------
extern "C" void kernel_launch(void* const* d_in, const int* in_sizes, int n_in,
                              void* d_out, int out_size) {
    const float* T    = (const float*)d_in[0];
    const float* Wq   = (const float*)d_in[1];
    const float* Wk   = (const float*)d_in[2];
    const float* Wv   = (const float*)d_in[3];
    const float* Wout = (const float*)d_in[4];
    const float* Rf   = (const float*)d_in[5];
    float* out = (float*)d_out;

    k_tsum<<<4104, 256>>>(T, Rf);
    k_p2a<<<dim3(ND / 128, CS_SPLIT), 128>>>(Wk, Wv);
    k_p2b<<<dim3(NC / 128, KS_SPLIT), 128>>>(Wq, Wout);
    k_s<<<dim3(SCH, NB), 256>>>(T);
    k_wout<<<dim3(NM / ITILE, NB, WSPLIT), 256>>>(out);
}

// round 13
// speedup vs baseline: 1.1092x; 1.1048x over previous
#include <cuda_runtime.h>
#include <math.h>

#define NB 32
#define NC 1024
#define NM 1024
#define ND 512
#define NR 64

#define CS_SPLIT 32             // c-chunks for p2a (32 c each)
#define KS_SPLIT 16             // d-chunks for p2b (32 d each)
#define D_CH (ND / KS_SPLIT)    // 32
#define ITILE 128               // i-tile for fused kernel

// ---- device scratch (static: no allocations allowed) ----
__device__ float g_tsum[NB * NC];
__device__ float g_rsum[NR];
__device__ float g_kpart[CS_SPLIT][NB * ND];
__device__ float g_vpart[CS_SPLIT][NB * ND];
__device__ float g_upart[KS_SPLIT][NB * NC];
__device__ float g_ypart[KS_SPLIT][NB * NC];

__device__ __forceinline__ float warp_sum(float v) {
    #pragma unroll
    for (int o = 16; o; o >>= 1) v += __shfl_down_sync(0xffffffffu, v, o);
    return v;
}

// ---------------------------------------------------------------------------
// k_tsum: blocks [0,4096): tsum[b,c] = sum_m T[b,c,m]  (warp/row, float4)
//         blocks [4096,4104): rsum[r] = sum_m R_full[r,m]
// ---------------------------------------------------------------------------
__global__ __launch_bounds__(256) void k_tsum(const float* __restrict__ T,
                                              const float* __restrict__ Rf) {
    if (blockIdx.x < 4096) {
        int row = blockIdx.x * 8 + (threadIdx.x >> 5);
        int lane = threadIdx.x & 31;
        const float4* T4 = reinterpret_cast<const float4*>(T) + (size_t)row * (NM / 4);
        float4 t[8];
        #pragma unroll
        for (int k = 0; k < 8; k++) t[k] = T4[k * 32 + lane];
        float acc = 0.f;
        #pragma unroll
        for (int k = 0; k < 8; k++)
            acc += (t[k].x + t[k].y) + (t[k].z + t[k].w);
        acc = warp_sum(acc);
        if (lane == 0) g_tsum[row] = acc;
    } else {
        int r = (blockIdx.x - 4096) * 8 + (threadIdx.x >> 5);   // 64 rows
        int lane = threadIdx.x & 31;
        const float4* R4 = reinterpret_cast<const float4*>(Rf) + (size_t)r * (NM / 4);
        float4 t[8];
        #pragma unroll
        for (int k = 0; k < 8; k++) t[k] = R4[k * 32 + lane];
        float acc = 0.f;
        #pragma unroll
        for (int k = 0; k < 8; k++)
            acc += (t[k].x + t[k].y) + (t[k].z + t[k].w);
        acc = warp_sum(acc);
        if (lane == 0) g_rsum[r] = acc;
    }
}

// ---------------------------------------------------------------------------
// k_p2a: kpart/vpart[cs][b,d] = sum_{c in chunk} tsum[b,c]*Wk/Wv[c,d]
// ---------------------------------------------------------------------------
__global__ __launch_bounds__(128) void k_p2a(const float* __restrict__ Wk,
                                             const float* __restrict__ Wv) {
    __shared__ float ts[NB][32];
    int d  = blockIdx.x * 128 + threadIdx.x;
    int c0 = blockIdx.y * 32;
    for (int e = threadIdx.x; e < NB * 32; e += 128)
        ts[e >> 5][e & 31] = g_tsum[(e >> 5) * NC + c0 + (e & 31)];
    __syncthreads();

    float aK[NB], aV[NB];
    #pragma unroll
    for (int b = 0; b < NB; b++) { aK[b] = 0.f; aV[b] = 0.f; }

    #pragma unroll 4
    for (int cc = 0; cc < 32; cc++) {
        int c = c0 + cc;
        float wk = Wk[(size_t)c * ND + d];
        float wv = Wv[(size_t)c * ND + d];
        #pragma unroll
        for (int b = 0; b < NB; b++) {
            float tv = ts[b][cc];
            aK[b] = fmaf(tv, wk, aK[b]);
            aV[b] = fmaf(tv, wv, aV[b]);
        }
    }
    #pragma unroll
    for (int b = 0; b < NB; b++) {
        g_kpart[blockIdx.y][b * ND + d] = aK[b];
        g_vpart[blockIdx.y][b * ND + d] = aV[b];
    }
}

// ---------------------------------------------------------------------------
// k_p2b: fuses kv-partial reduction + both GEMMs (no Wq transpose).
// ---------------------------------------------------------------------------
__global__ __launch_bounds__(128) void k_p2b(const float* __restrict__ Wq,
                                             const float* __restrict__ Wout) {
    __shared__ float ks[NB][D_CH], vs[NB][D_CH];
    int c  = blockIdx.x * 128 + threadIdx.x;
    int d0 = blockIdx.y * D_CH;

    for (int e = threadIdx.x; e < NB * D_CH; e += 128) {
        int addr = (e >> 5) * ND + d0 + (e & (D_CH - 1));
        float sk = 0.f, sv = 0.f;
        #pragma unroll
        for (int p = 0; p < CS_SPLIT; p++) {
            sk += g_kpart[p][addr];
            sv += g_vpart[p][addr];
        }
        ks[e >> 5][e & (D_CH - 1)] = sk;
        vs[e >> 5][e & (D_CH - 1)] = sv;
    }
    __syncthreads();

    float wqr[D_CH];
    {
        const float4* wq4 = reinterpret_cast<const float4*>(Wq + (size_t)c * ND + d0);
        #pragma unroll
        for (int q = 0; q < D_CH / 4; q++) {
            float4 v = wq4[q];
            wqr[q * 4 + 0] = v.x; wqr[q * 4 + 1] = v.y;
            wqr[q * 4 + 2] = v.z; wqr[q * 4 + 3] = v.w;
        }
    }

    float aU[NB], aY[NB];
    #pragma unroll
    for (int b = 0; b < NB; b++) { aU[b] = 0.f; aY[b] = 0.f; }

    #pragma unroll 4
    for (int dd = 0; dd < D_CH; dd++) {
        float wq = wqr[dd];
        float wo = Wout[(size_t)(d0 + dd) * NC + c];
        #pragma unroll
        for (int b = 0; b < NB; b++) {
            aU[b] = fmaf(ks[b][dd], wq, aU[b]);
            aY[b] = fmaf(vs[b][dd], wo, aY[b]);
        }
    }
    #pragma unroll
    for (int b = 0; b < NB; b++) {
        g_upart[blockIdx.y][b * NC + c] = aU[b];
        g_ypart[blockIdx.y][b * NC + c] = aY[b];
    }
}

// ---------------------------------------------------------------------------
// k_fused: block = (i-tile of 128, b); 256 threads; grid (8, 32).
//  A: reduce upart->us[1024], ypart->y_s[1024], rsum->rs
//  B: s[i] = scale * sum_c us[c]*T[b,c,i]  — 8 c-interleaved warp groups,
//     each lane owns a float4 of i; deterministic 8-way smem reduce
//     -> softmax -> w_s[i]
//  C: out[b,c,i-tile] = w * y[c]  (streaming stores)
// No g_spart, no separate k_s / k_wout launches.
// ---------------------------------------------------------------------------
__global__ __launch_bounds__(256) void k_fused(const float* __restrict__ T,
                                               float* __restrict__ out) {
    __shared__ float us[NC];
    __shared__ float y_s[NC];
    __shared__ float rs[NR];
    __shared__ __align__(16) float w_s[ITILE];
    __shared__ __align__(16) float4 sred[8][32];   // [c-group][i-lane]
    int b   = blockIdx.y;
    int i0  = blockIdx.x * ITILE;
    int tid = threadIdx.x;

    // phase A
    if (tid < NR) rs[tid] = g_rsum[tid];
    for (int e = tid; e < NC; e += 256) {
        float su = 0.f, sy = 0.f;
        #pragma unroll
        for (int p = 0; p < KS_SPLIT; p++) {
            su += g_upart[p][b * NC + e];
            sy += g_ypart[p][b * NC + e];
        }
        us[e] = su;
        y_s[e] = sy;
    }
    __syncthreads();

    // phase B: c-interleaved dot products. group g = tid>>5 handles c ≡ g (mod 8);
    // lane owns i = i0 + 4*lane .. 4*lane+3 (float4).
    {
        int g    = tid >> 5;
        int lane = tid & 31;
        const float* Tp = T + ((size_t)b * NC + g) * NM + i0 + 4 * lane;
        float4 acc = {0.f, 0.f, 0.f, 0.f};
        #pragma unroll 8
        for (int k = 0; k < NC / 8; k++) {
            float4 t = *reinterpret_cast<const float4*>(Tp + (size_t)k * 8 * NM);
            float u = us[g + 8 * k];
            acc.x = fmaf(u, t.x, acc.x);
            acc.y = fmaf(u, t.y, acc.y);
            acc.z = fmaf(u, t.z, acc.z);
            acc.w = fmaf(u, t.w, acc.w);
        }
        sred[g][lane] = acc;
    }
    __syncthreads();

    // reduce 8 groups (fixed order -> deterministic), softmax
    if (tid < ITILE) {
        const float* sf = reinterpret_cast<const float*>(sred);
        int base = (tid >> 2) * 4 + (tid & 3);       // index within one group's 128
        float s = 0.f;
        #pragma unroll
        for (int g = 0; g < 8; g++)
            s += sf[g * ITILE + base];
        s *= 0.044194173824159216f;   // 1/sqrt(512)

        float mx = -1e30f;
        #pragma unroll
        for (int r = 0; r < NR; r++) mx = fmaxf(mx, s * rs[r]);
        float sp = 0.f, spr = 0.f;
        #pragma unroll
        for (int r = 0; r < NR; r++) {
            float p = __expf(fmaf(s, rs[r], -mx));
            sp += p;
            spr = fmaf(p, rs[r], spr);
        }
        w_s[tid] = spr / sp;
    }
    __syncthreads();

    // phase C: streaming broadcast write
    int ci = tid >> 5;                 // 0..7
    int i4 = tid & 31;                 // float4 lane within i-tile
    float4 w4 = reinterpret_cast<const float4*>(w_s)[i4];
    float4* O4 = reinterpret_cast<float4*>(out);
    #pragma unroll 4
    for (int c = ci; c < NC; c += 8) {
        float yv = y_s[c];
        float4 o;
        o.x = w4.x * yv; o.y = w4.y * yv; o.z = w4.z * yv; o.w = w4.w * yv;
        __stcs(&O4[((size_t)(b * NC + c) * NM + i0) / 4 + i4], o);
    }
}

// ---------------------------------------------------------------------------
extern "C" void kernel_launch(void* const* d_in, const int* in_sizes, int n_in,
                              void* d_out, int out_size) {
    const float* T    = (const float*)d_in[0];
    const float* Wq   = (const float*)d_in[1];
    const float* Wk   = (const float*)d_in[2];
    const float* Wv   = (const float*)d_in[3];
    const float* Wout = (const float*)d_in[4];
    const float* Rf   = (const float*)d_in[5];
    float* out = (float*)d_out;

    k_tsum<<<4104, 256>>>(T, Rf);
    k_p2a<<<dim3(ND / 128, CS_SPLIT), 128>>>(Wk, Wv);
    k_p2b<<<dim3(NC / 128, KS_SPLIT), 128>>>(Wq, Wout);
    k_fused<<<dim3(NM / ITILE, NB), 256>>>(T, out);
}